// round 14
// baseline (speedup 1.0000x reference)
#include <cuda_runtime.h>
#include <cuda_fp16.h>
#include <cstdint>

// N_NODES=50000, N_EDGES=800000, IN=128, HID=128, OUT=64. int32 edge indices.
#define NMAX 50048
#define PAD 64
#define IN_DIM 128
#define HID_DIM 128
#define OUT_DIM 64

__device__ int    g_cnt[NMAX];              // fill cursor; re-zeroed by dinv_kernel
__device__ int    g_deg[NMAX];              // clamped degree
__device__ int    g_csr[NMAX * PAD];
__device__ float  g_dinv[NMAX];
__device__ __half g_h1[NMAX * HID_DIM];
__device__ float  g_acc1[NMAX * HID_DIM];
__device__ float  g_h2[NMAX * OUT_DIM];

__device__ __forceinline__ float to_tf32(float x) {
    float r;
    asm("cvt.rna.tf32.f32 %0, %1;" : "=f"(r) : "f"(x));
    return r;
}

// ---------------------------------------------------------------------------
__global__ void fill_kernel(const int* __restrict__ src, const int* __restrict__ dst,
                            int* __restrict__ cnt, int* __restrict__ csr, int E) {
    int e = blockIdx.x * blockDim.x + threadIdx.x;
    if (e < E) {
        int d = dst[e];
        int pos = atomicAdd(&cnt[d], 1);
        if (pos < PAD) csr[d * PAD + pos] = src[e];
    }
}

// deg/dinv extraction + cnt re-zero (keeps graph replay deterministic, kills memset launch)
__global__ void dinv_kernel(int* __restrict__ cnt, int* __restrict__ deg,
                            float* __restrict__ dinv, int N) {
    int i = blockIdx.x * blockDim.x + threadIdx.x;
    if (i < N) {
        int d = cnt[i];
        deg[i] = min(d, PAD);
        dinv[i] = d > 0 ? rsqrtf((float)d) : 0.0f;
        cnt[i] = 0;
    }
}

// ---------------------------------------------------------------------------
// Tensor-core GEMM (R13, known-good): mma.sync.m16n8k8 tf32, fp32 accum.
template <int K, int N, bool RELU, bool HALF_OUT>
__global__ void gemm_tc_kernel(const float* __restrict__ X, const float* __restrict__ W,
                               const float* __restrict__ scale,
                               float* __restrict__ Y, int M) {
    constexpr int XS = K + 12;
    constexpr int WS = N + 12;
    constexpr int CHUNKS = N / 16;
    extern __shared__ float smem[];
    float* Ws = smem;
    float* Xs = smem + K * WS;

    int t = threadIdx.x;
    for (int i = t; i < K * N / 4; i += 256) {
        int k = i / (N / 4), n4 = i % (N / 4);
        float4 w = ((const float4*)W)[(size_t)k * (N / 4) + n4];
        w.x = to_tf32(w.x); w.y = to_tf32(w.y); w.z = to_tf32(w.z); w.w = to_tf32(w.w);
        ((float4*)(Ws + k * WS))[n4] = w;
    }
    int row0 = blockIdx.x * 64;
    constexpr int K4 = K / 4;
    for (int i = t; i < 64 * K4; i += 256) {
        int r = i / K4, c4 = i % K4;
        int gr = row0 + r;
        float4 v = make_float4(0.f, 0.f, 0.f, 0.f);
        if (gr < M) v = ((const float4*)X)[(size_t)gr * K4 + c4];
        if (RELU) {
            v.x = fmaxf(v.x, 0.f); v.y = fmaxf(v.y, 0.f);
            v.z = fmaxf(v.z, 0.f); v.w = fmaxf(v.w, 0.f);
        }
        v.x = to_tf32(v.x); v.y = to_tf32(v.y); v.z = to_tf32(v.z); v.w = to_tf32(v.w);
        ((float4*)(Xs + r * XS))[c4] = v;
    }
    __syncthreads();

    int wid = t >> 5, lane = t & 31;
    int gid = lane >> 2, tig = lane & 3;
    int rowbase = (wid & 3) * 16;
    int colbase = (wid >> 2) * (N / 2);

    float acc[CHUNKS][4];
#pragma unroll
    for (int c = 0; c < CHUNKS; c++)
#pragma unroll
        for (int j = 0; j < 4; j++) acc[c][j] = 0.f;

#pragma unroll
    for (int ks = 0; ks < K / 8; ks++) {
        int kb = ks * 8;
        const float* xp = Xs + (rowbase + gid) * XS + kb + tig;
        unsigned a0 = __float_as_uint(xp[0]);
        unsigned a1 = __float_as_uint(xp[8 * XS]);
        unsigned a2 = __float_as_uint(xp[4]);
        unsigned a3 = __float_as_uint(xp[8 * XS + 4]);
        const float* wp = Ws + (kb + tig) * WS + colbase + gid;
#pragma unroll
        for (int ch = 0; ch < CHUNKS; ch++) {
            unsigned b0 = __float_as_uint(wp[ch * 8]);
            unsigned b1 = __float_as_uint(wp[4 * WS + ch * 8]);
            asm volatile(
                "mma.sync.aligned.m16n8k8.row.col.f32.tf32.tf32.f32 "
                "{%0,%1,%2,%3}, {%4,%5,%6,%7}, {%8,%9}, {%0,%1,%2,%3};"
                : "+f"(acc[ch][0]), "+f"(acc[ch][1]), "+f"(acc[ch][2]), "+f"(acc[ch][3])
                : "r"(a0), "r"(a1), "r"(a2), "r"(a3), "r"(b0), "r"(b1));
        }
    }

    int r0 = row0 + rowbase + gid;
    int r1 = r0 + 8;
    float s0 = (r0 < M) ? scale[r0] : 0.f;
    float s1 = (r1 < M) ? scale[r1] : 0.f;
#pragma unroll
    for (int ch = 0; ch < CHUNKS; ch++) {
        int gn = colbase + ch * 8 + 2 * tig;
        if (HALF_OUT) {
            __half* Yh = (__half*)Y;
            if (r0 < M) {
                __half2 p = __floats2half2_rn(acc[ch][0] * s0, acc[ch][1] * s0);
                *(__half2*)(Yh + (size_t)r0 * N + gn) = p;
            }
            if (r1 < M) {
                __half2 p = __floats2half2_rn(acc[ch][2] * s1, acc[ch][3] * s1);
                *(__half2*)(Yh + (size_t)r1 * N + gn) = p;
            }
        } else {
            if (r0 < M)
                *(float2*)(Y + (size_t)r0 * N + gn) = make_float2(acc[ch][0] * s0, acc[ch][1] * s0);
            if (r1 < M)
                *(float2*)(Y + (size_t)r1 * N + gn) = make_float2(acc[ch][2] * s1, acc[ch][3] * s1);
        }
    }
}

// ---------------------------------------------------------------------------
// Agg C=128 over fp16 h: FOUR warps per node = (2 col-halves) x (2 edge-parity).
// Each warp: ~deg/2 edges = one MLP-8 batch. Parity partials combined via smem.
__global__ void agg128_kernel(const int* __restrict__ deg, const int* __restrict__ csr,
                              const __half* __restrict__ h, const float* __restrict__ dinv,
                              const float* __restrict__ bias, float* __restrict__ out, int N) {
    __shared__ float2 part[2][2][32];   // [node_local][colhalf][lane]
    int w = threadIdx.x >> 5;           // 0..7
    int lane = threadIdx.x & 31;
    int node_local = w >> 2;
    int colhalf = w & 1;
    int par = (w >> 1) & 1;
    int node = blockIdx.x * 2 + node_local;
    bool active = node < N;

    float2 acc = make_float2(0.f, 0.f);
    int col = colhalf * 32 + lane;
    if (active) {
        int d = deg[node];
        int h1cnt = (d + 1) >> 1;
        int j = node * PAD + (par ? h1cnt : 0);
        int end = node * PAD + (par ? d : h1cnt);
        const unsigned* hv = (const unsigned*)h;
        for (; j + 8 <= end; j += 8) {
            int s[8];
#pragma unroll
            for (int u = 0; u < 8; u++) s[u] = csr[j + u];
            unsigned v[8];
#pragma unroll
            for (int u = 0; u < 8; u++) v[u] = hv[(size_t)s[u] * 64 + col];
#pragma unroll
            for (int u = 0; u < 8; u++) {
                float2 f = __half22float2(*(__half2*)&v[u]);
                acc.x += f.x; acc.y += f.y;
            }
        }
        for (; j < end; j++) {
            unsigned a = ((const unsigned*)h)[(size_t)csr[j] * 64 + col];
            float2 f = __half22float2(*(__half2*)&a);
            acc.x += f.x; acc.y += f.y;
        }
    }
    if (par == 1) part[node_local][colhalf][lane] = acc;
    __syncthreads();
    if (active && par == 0) {
        float2 p = part[node_local][colhalf][lane];
        acc.x += p.x; acc.y += p.y;
        float dn = dinv[node];
        float2 bv = ((const float2*)bias)[col];
        float2 o = make_float2(acc.x * dn + bv.x, acc.y * dn + bv.y);
        ((float2*)out)[(size_t)node * 64 + col] = o;
    }
}

// Agg C=64 over fp32 h: FOUR warps per node (2 col-halves x 2 edge-parity).
__global__ void agg64_kernel(const int* __restrict__ deg, const int* __restrict__ csr,
                             const float* __restrict__ h, const float* __restrict__ dinv,
                             const float* __restrict__ bias, float* __restrict__ out, int N) {
    __shared__ float part[2][2][32];
    int w = threadIdx.x >> 5;
    int lane = threadIdx.x & 31;
    int node_local = w >> 2;
    int colhalf = w & 1;
    int par = (w >> 1) & 1;
    int node = blockIdx.x * 2 + node_local;
    bool active = node < N;

    float acc = 0.f;
    int col = colhalf * 32 + lane;
    if (active) {
        int d = deg[node];
        int h1cnt = (d + 1) >> 1;
        int j = node * PAD + (par ? h1cnt : 0);
        int end = node * PAD + (par ? d : h1cnt);
        for (; j + 8 <= end; j += 8) {
            int s[8];
#pragma unroll
            for (int u = 0; u < 8; u++) s[u] = csr[j + u];
            float v[8];
#pragma unroll
            for (int u = 0; u < 8; u++) v[u] = h[(size_t)s[u] * 64 + col];
#pragma unroll
            for (int u = 0; u < 8; u++) acc += v[u];
        }
        for (; j < end; j++) acc += h[(size_t)csr[j] * 64 + col];
    }
    if (par == 1) part[node_local][colhalf][lane] = acc;
    __syncthreads();
    if (active && par == 0) {
        acc += part[node_local][colhalf][lane];
        out[(size_t)node * 64 + col] = acc * dinv[node] + bias[col];
    }
}

// ---------------------------------------------------------------------------
extern "C" void kernel_launch(void* const* d_in, const int* in_sizes, int n_in,
                              void* d_out, int out_size) {
    const float* x  = (const float*)d_in[0];
    const int*   ei = (const int*)d_in[1];
    const float* W1 = (const float*)d_in[2];
    const float* b1 = (const float*)d_in[3];
    const float* W2 = (const float*)d_in[4];
    const float* b2 = (const float*)d_in[5];
    float* out = (float*)d_out;

    const int N = in_sizes[0] / IN_DIM;
    const int E = in_sizes[1] / 2;
    const int* src = ei;
    const int* dst = ei + E;

    int *p_cnt, *p_deg, *p_csr;
    float *p_dinv, *p_acc1, *p_h2;
    __half* p_h1;
    cudaGetSymbolAddress((void**)&p_cnt,  g_cnt);
    cudaGetSymbolAddress((void**)&p_deg,  g_deg);
    cudaGetSymbolAddress((void**)&p_csr,  g_csr);
    cudaGetSymbolAddress((void**)&p_dinv, g_dinv);
    cudaGetSymbolAddress((void**)&p_h1,   g_h1);
    cudaGetSymbolAddress((void**)&p_acc1, g_acc1);
    cudaGetSymbolAddress((void**)&p_h2,   g_h2);

    const int smem1 = (IN_DIM * (HID_DIM + 12) + 64 * (IN_DIM + 12)) * 4;
    const int smem2 = (HID_DIM * (OUT_DIM + 12) + 64 * (HID_DIM + 12)) * 4;
    cudaFuncSetAttribute((const void*)gemm_tc_kernel<IN_DIM, HID_DIM, false, true>,
                         cudaFuncAttributeMaxDynamicSharedMemorySize, smem1);
    cudaFuncSetAttribute((const void*)gemm_tc_kernel<HID_DIM, OUT_DIM, true, false>,
                         cudaFuncAttributeMaxDynamicSharedMemorySize, smem2);

    // Build: cnt is zero on first call (static init) and re-zeroed by dinv_kernel
    // at the end of every call -> graph replays stay deterministic, no memset launch.
    fill_kernel<<<(E + 255) / 256, 256>>>(src, dst, p_cnt, p_csr, E);
    dinv_kernel<<<(N + 255) / 256, 256>>>(p_cnt, p_deg, p_dinv, N);

    // layer 1
    gemm_tc_kernel<IN_DIM, HID_DIM, false, true>
        <<<(N + 63) / 64, 256, smem1>>>(x, W1, p_dinv, (float*)p_h1, N);
    agg128_kernel<<<(N + 1) / 2, 256>>>(p_deg, p_csr, p_h1, p_dinv, b1, p_acc1, N);

    // layer 2
    gemm_tc_kernel<HID_DIM, OUT_DIM, true, false>
        <<<(N + 63) / 64, 256, smem2>>>(p_acc1, W2, p_dinv, p_h2, N);
    agg64_kernel<<<(N + 1) / 2, 256>>>(p_deg, p_csr, p_h2, p_dinv, b2, out, N);
}

// round 15
// speedup vs baseline: 1.1701x; 1.1701x over previous
#include <cuda_runtime.h>
#include <cuda_fp16.h>
#include <cstdint>

// N_NODES=50000, N_EDGES=800000, IN=128, HID=128, OUT=64. int32 edge indices.
#define NMAX 50048
#define PAD 64
#define IN_DIM 128
#define HID_DIM 128
#define OUT_DIM 64

__device__ int    g_cnt[NMAX];       // degree counter; zeroed by dinv for next call
__device__ int    g_cursor[NMAX];    // fill cursor; zeroed by dinv for this call
__device__ int    g_deg[NMAX];       // clamped degree
__device__ int    g_csr[NMAX * PAD];
__device__ float  g_dinv[NMAX];
__device__ __half g_h1[NMAX * HID_DIM];
__device__ float  g_acc1[NMAX * HID_DIM];
__device__ float  g_h2[NMAX * OUT_DIM];

__device__ __forceinline__ float to_tf32(float x) {
    float r;
    asm("cvt.rna.tf32.f32 %0, %1;" : "=f"(r) : "f"(x));
    return r;
}

// ---------------------------------------------------------------------------
__global__ void deg_kernel(const int* __restrict__ dst, int* __restrict__ cnt, int E) {
    int i = blockIdx.x * blockDim.x + threadIdx.x;
    if (i < E) atomicAdd(&cnt[dst[i]], 1);
}

// deg/dinv extraction; zero cnt (next call) and cursor (this call's fill).
__global__ void dinv_kernel(int* __restrict__ cnt, int* __restrict__ cursor,
                            int* __restrict__ deg, float* __restrict__ dinv, int N) {
    int i = blockIdx.x * blockDim.x + threadIdx.x;
    if (i < N) {
        int d = cnt[i];
        deg[i] = min(d, PAD);
        dinv[i] = d > 0 ? rsqrtf((float)d) : 0.0f;
        cnt[i] = 0;
        cursor[i] = 0;
    }
}

__global__ void fill_kernel(const int* __restrict__ src, const int* __restrict__ dst,
                            int* __restrict__ cursor, int* __restrict__ csr, int E) {
    int e = blockIdx.x * blockDim.x + threadIdx.x;
    if (e < E) {
        int d = dst[e];
        int pos = atomicAdd(&cursor[d], 1);
        if (pos < PAD) csr[d * PAD + pos] = src[e];
    }
}

// ---------------------------------------------------------------------------
// Tensor-core GEMM (R13, known-good): mma.sync.m16n8k8 tf32, fp32 accum.
template <int K, int N, bool RELU, bool HALF_OUT>
__global__ void gemm_tc_kernel(const float* __restrict__ X, const float* __restrict__ W,
                               const float* __restrict__ scale,
                               float* __restrict__ Y, int M) {
    constexpr int XS = K + 12;
    constexpr int WS = N + 12;
    constexpr int CHUNKS = N / 16;
    extern __shared__ float smem[];
    float* Ws = smem;
    float* Xs = smem + K * WS;

    int t = threadIdx.x;
    for (int i = t; i < K * N / 4; i += 256) {
        int k = i / (N / 4), n4 = i % (N / 4);
        float4 w = ((const float4*)W)[(size_t)k * (N / 4) + n4];
        w.x = to_tf32(w.x); w.y = to_tf32(w.y); w.z = to_tf32(w.z); w.w = to_tf32(w.w);
        ((float4*)(Ws + k * WS))[n4] = w;
    }
    int row0 = blockIdx.x * 64;
    constexpr int K4 = K / 4;
    for (int i = t; i < 64 * K4; i += 256) {
        int r = i / K4, c4 = i % K4;
        int gr = row0 + r;
        float4 v = make_float4(0.f, 0.f, 0.f, 0.f);
        if (gr < M) v = ((const float4*)X)[(size_t)gr * K4 + c4];
        if (RELU) {
            v.x = fmaxf(v.x, 0.f); v.y = fmaxf(v.y, 0.f);
            v.z = fmaxf(v.z, 0.f); v.w = fmaxf(v.w, 0.f);
        }
        v.x = to_tf32(v.x); v.y = to_tf32(v.y); v.z = to_tf32(v.z); v.w = to_tf32(v.w);
        ((float4*)(Xs + r * XS))[c4] = v;
    }
    __syncthreads();

    int wid = t >> 5, lane = t & 31;
    int gid = lane >> 2, tig = lane & 3;
    int rowbase = (wid & 3) * 16;
    int colbase = (wid >> 2) * (N / 2);

    float acc[CHUNKS][4];
#pragma unroll
    for (int c = 0; c < CHUNKS; c++)
#pragma unroll
        for (int j = 0; j < 4; j++) acc[c][j] = 0.f;

#pragma unroll
    for (int ks = 0; ks < K / 8; ks++) {
        int kb = ks * 8;
        const float* xp = Xs + (rowbase + gid) * XS + kb + tig;
        unsigned a0 = __float_as_uint(xp[0]);
        unsigned a1 = __float_as_uint(xp[8 * XS]);
        unsigned a2 = __float_as_uint(xp[4]);
        unsigned a3 = __float_as_uint(xp[8 * XS + 4]);
        const float* wp = Ws + (kb + tig) * WS + colbase + gid;
#pragma unroll
        for (int ch = 0; ch < CHUNKS; ch++) {
            unsigned b0 = __float_as_uint(wp[ch * 8]);
            unsigned b1 = __float_as_uint(wp[4 * WS + ch * 8]);
            asm volatile(
                "mma.sync.aligned.m16n8k8.row.col.f32.tf32.tf32.f32 "
                "{%0,%1,%2,%3}, {%4,%5,%6,%7}, {%8,%9}, {%0,%1,%2,%3};"
                : "+f"(acc[ch][0]), "+f"(acc[ch][1]), "+f"(acc[ch][2]), "+f"(acc[ch][3])
                : "r"(a0), "r"(a1), "r"(a2), "r"(a3), "r"(b0), "r"(b1));
        }
    }

    int r0 = row0 + rowbase + gid;
    int r1 = r0 + 8;
    float s0 = (r0 < M) ? scale[r0] : 0.f;
    float s1 = (r1 < M) ? scale[r1] : 0.f;
#pragma unroll
    for (int ch = 0; ch < CHUNKS; ch++) {
        int gn = colbase + ch * 8 + 2 * tig;
        if (HALF_OUT) {
            __half* Yh = (__half*)Y;
            if (r0 < M) {
                __half2 p = __floats2half2_rn(acc[ch][0] * s0, acc[ch][1] * s0);
                *(__half2*)(Yh + (size_t)r0 * N + gn) = p;
            }
            if (r1 < M) {
                __half2 p = __floats2half2_rn(acc[ch][2] * s1, acc[ch][3] * s1);
                *(__half2*)(Yh + (size_t)r1 * N + gn) = p;
            }
        } else {
            if (r0 < M)
                *(float2*)(Y + (size_t)r0 * N + gn) = make_float2(acc[ch][0] * s0, acc[ch][1] * s0);
            if (r1 < M)
                *(float2*)(Y + (size_t)r1 * N + gn) = make_float2(acc[ch][2] * s1, acc[ch][3] * s1);
        }
    }
}

// ---------------------------------------------------------------------------
// Agg C=128 over fp16 h: TWO warps per node (R12, measured 36.6us).
__global__ void agg128_kernel(const int* __restrict__ deg, const int* __restrict__ csr,
                              const __half* __restrict__ h, const float* __restrict__ dinv,
                              const float* __restrict__ bias, float* __restrict__ out, int N) {
    int wp = (blockIdx.x * blockDim.x + threadIdx.x) >> 5;
    int lane = threadIdx.x & 31;
    int node = wp >> 1;
    int half = wp & 1;
    if (node >= N) return;
    int d = deg[node];
    int j = node * PAD, end = j + d;
    int col = half * 32 + lane;
    const unsigned* hv = (const unsigned*)h;
    float2 acc = make_float2(0.f, 0.f);
    for (; j + 8 <= end; j += 8) {
        int s[8];
#pragma unroll
        for (int u = 0; u < 8; u++) s[u] = csr[j + u];
        unsigned v[8];
#pragma unroll
        for (int u = 0; u < 8; u++) v[u] = hv[(size_t)s[u] * 64 + col];
#pragma unroll
        for (int u = 0; u < 8; u++) {
            float2 f = __half22float2(*(__half2*)&v[u]);
            acc.x += f.x; acc.y += f.y;
        }
    }
    for (; j < end; j++) {
        unsigned a = hv[(size_t)csr[j] * 64 + col];
        float2 f = __half22float2(*(__half2*)&a);
        acc.x += f.x; acc.y += f.y;
    }
    float dn = dinv[node];
    float2 bv = ((const float2*)bias)[col];
    float2 o = make_float2(acc.x * dn + bv.x, acc.y * dn + bv.y);
    ((float2*)out)[(size_t)node * 64 + col] = o;
}

// Agg C=64 over fp32 h: TWO warps per node (R12, known-good).
__global__ void agg64_kernel(const int* __restrict__ deg, const int* __restrict__ csr,
                             const float* __restrict__ h, const float* __restrict__ dinv,
                             const float* __restrict__ bias, float* __restrict__ out, int N) {
    int wp = (blockIdx.x * blockDim.x + threadIdx.x) >> 5;
    int lane = threadIdx.x & 31;
    int node = wp >> 1;
    int half = wp & 1;
    if (node >= N) return;
    int d = deg[node];
    int j = node * PAD, end = j + d;
    int col = half * 32 + lane;
    float acc = 0.f;
    for (; j + 8 <= end; j += 8) {
        int s[8];
#pragma unroll
        for (int u = 0; u < 8; u++) s[u] = csr[j + u];
        float v[8];
#pragma unroll
        for (int u = 0; u < 8; u++) v[u] = h[(size_t)s[u] * 64 + col];
#pragma unroll
        for (int u = 0; u < 8; u++) acc += v[u];
    }
    for (; j < end; j++) acc += h[(size_t)csr[j] * 64 + col];
    out[(size_t)node * 64 + col] = acc * dinv[node] + bias[col];
}

// ---------------------------------------------------------------------------
extern "C" void kernel_launch(void* const* d_in, const int* in_sizes, int n_in,
                              void* d_out, int out_size) {
    const float* x  = (const float*)d_in[0];
    const int*   ei = (const int*)d_in[1];
    const float* W1 = (const float*)d_in[2];
    const float* b1 = (const float*)d_in[3];
    const float* W2 = (const float*)d_in[4];
    const float* b2 = (const float*)d_in[5];
    float* out = (float*)d_out;

    const int N = in_sizes[0] / IN_DIM;
    const int E = in_sizes[1] / 2;
    const int* src = ei;
    const int* dst = ei + E;

    int *p_cnt, *p_cursor, *p_deg, *p_csr;
    float *p_dinv, *p_acc1, *p_h2;
    __half* p_h1;
    cudaGetSymbolAddress((void**)&p_cnt,    g_cnt);
    cudaGetSymbolAddress((void**)&p_cursor, g_cursor);
    cudaGetSymbolAddress((void**)&p_deg,    g_deg);
    cudaGetSymbolAddress((void**)&p_csr,    g_csr);
    cudaGetSymbolAddress((void**)&p_dinv,   g_dinv);
    cudaGetSymbolAddress((void**)&p_h1,     g_h1);
    cudaGetSymbolAddress((void**)&p_acc1,   g_acc1);
    cudaGetSymbolAddress((void**)&p_h2,     g_h2);

    const int smem1 = (IN_DIM * (HID_DIM + 12) + 64 * (IN_DIM + 12)) * 4;
    const int smem2 = (HID_DIM * (OUT_DIM + 12) + 64 * (HID_DIM + 12)) * 4;
    cudaFuncSetAttribute((const void*)gemm_tc_kernel<IN_DIM, HID_DIM, false, true>,
                         cudaFuncAttributeMaxDynamicSharedMemorySize, smem1);
    cudaFuncSetAttribute((const void*)gemm_tc_kernel<HID_DIM, OUT_DIM, true, false>,
                         cudaFuncAttributeMaxDynamicSharedMemorySize, smem2);

    // One-time stream/event setup (first call is outside graph capture).
    static cudaStream_t s_side = nullptr;
    static cudaEvent_t  s_fork = nullptr, s_join = nullptr;
    if (!s_side) {
        cudaStreamCreateWithFlags(&s_side, cudaStreamNonBlocking);
        cudaEventCreateWithFlags(&s_fork, cudaEventDisableTiming);
        cudaEventCreateWithFlags(&s_join, cudaEventDisableTiming);
    }

    // --- serial prefix: deg -> dinv (zeroes cnt for next call, cursor for fill) ---
    // cnt/cursor are static-zero on first call, re-zeroed by dinv each call.
    deg_kernel<<<(E + 255) / 256, 256>>>(dst, p_cnt, E);
    dinv_kernel<<<(N + 255) / 256, 256>>>(p_cnt, p_cursor, p_deg, p_dinv, N);

    // --- fork: fill on side stream || GEMM1 (needs dinv only) on main ---
    cudaEventRecord(s_fork, 0);
    cudaStreamWaitEvent(s_side, s_fork, 0);
    fill_kernel<<<(E + 255) / 256, 256, 0, s_side>>>(src, dst, p_cursor, p_csr, E);
    cudaEventRecord(s_join, s_side);

    gemm_tc_kernel<IN_DIM, HID_DIM, false, true>
        <<<(N + 63) / 64, 256, smem1>>>(x, W1, p_dinv, (float*)p_h1, N);

    cudaStreamWaitEvent(0, s_join, 0);

    // --- layer 1 aggregation ---
    agg128_kernel<<<(N * 2 * 32 + 255) / 256, 256>>>(p_deg, p_csr, p_h1, p_dinv, b1, p_acc1, N);

    // --- layer 2 ---
    gemm_tc_kernel<HID_DIM, OUT_DIM, true, false>
        <<<(N + 63) / 64, 256, smem2>>>(p_acc1, W2, p_dinv, p_h2, N);
    agg64_kernel<<<(N * 2 * 32 + 255) / 256, 256>>>(p_deg, p_csr, p_h2, p_dinv, b2, out, N);
}

// round 16
// speedup vs baseline: 1.2115x; 1.0354x over previous
#include <cuda_runtime.h>
#include <cuda_fp16.h>
#include <cstdint>

// N_NODES=50000, N_EDGES=800000, IN=128, HID=128, OUT=64. int32 edge indices.
#define NMAX 50048
#define PAD 64
#define IN_DIM 128
#define HID_DIM 128
#define OUT_DIM 64

__device__ int    g_cnt[NMAX];       // degree counter; zeroed by dinv for next call
__device__ int    g_cursor[NMAX];    // fill cursor; zeroed by dinv for this call
__device__ int    g_deg[NMAX];
__device__ int    g_csr[NMAX * PAD];
__device__ float  g_dinv[NMAX];
__device__ __half g_h1[NMAX * HID_DIM];
__device__ float  g_acc1[NMAX * HID_DIM];
__device__ float  g_h2[NMAX * OUT_DIM];

// ---------------------------------------------------------------------------
__global__ void deg_kernel(const int* __restrict__ dst, int* __restrict__ cnt, int E) {
    int i = blockIdx.x * blockDim.x + threadIdx.x;
    if (i < E) atomicAdd(&cnt[dst[i]], 1);
}

__global__ void dinv_kernel(int* __restrict__ cnt, int* __restrict__ cursor,
                            int* __restrict__ deg, float* __restrict__ dinv, int N) {
    int i = blockIdx.x * blockDim.x + threadIdx.x;
    if (i < N) {
        int d = cnt[i];
        deg[i] = min(d, PAD);
        dinv[i] = d > 0 ? rsqrtf((float)d) : 0.0f;
        cnt[i] = 0;
        cursor[i] = 0;
    }
}

__global__ void fill_kernel(const int* __restrict__ src, const int* __restrict__ dst,
                            int* __restrict__ cursor, int* __restrict__ csr, int E) {
    int e = blockIdx.x * blockDim.x + threadIdx.x;
    if (e < E) {
        int d = dst[e];
        int pos = atomicAdd(&cursor[d], 1);
        if (pos < PAD) csr[d * PAD + pos] = src[e];
    }
}

// ---------------------------------------------------------------------------
// fp16 tensor-core GEMM: Y[M,N] = act(X)[M,K] @ W[K,N], Y[row] *= scale[row].
// mma.sync.m16n8k16.f32.f16.f16.f32. W stored TRANSPOSED in smem: Wt[n][k].
// Per k16-step: 4 A-loads + 2/chunk B-loads (all half2 = 4B LDS), CHUNKS MMAs.
// KS = K+8 halves -> conflict-free (bank = (4*gid+tig)%32, distinct).
template <int K, int N, bool RELU, bool HALF_OUT>
__global__ void gemm_h16_kernel(const float* __restrict__ X, const float* __restrict__ W,
                                const float* __restrict__ scale,
                                float* __restrict__ Y, int M) {
    constexpr int KS = K + 8;                 // row stride in halves
    constexpr int CHUNKS = N / 16;            // 8 (N=128) / 4 (N=64)
    extern __shared__ __half smh[];
    __half* Ws = smh;                         // N * KS   (transposed W)
    __half* Xs = smh + N * KS;                // 64 * KS

    int t = threadIdx.x;
    // W[k][n] -> Wt[n][k] fp16 (coalesced read, scattered 2B writes - one-time)
    for (int i = t; i < K * N / 4; i += 256) {
        int k = i / (N / 4), n4 = (i % (N / 4)) * 4;
        float4 w = ((const float4*)W)[i];
        Ws[(n4 + 0) * KS + k] = __float2half(w.x);
        Ws[(n4 + 1) * KS + k] = __float2half(w.y);
        Ws[(n4 + 2) * KS + k] = __float2half(w.z);
        Ws[(n4 + 3) * KS + k] = __float2half(w.w);
    }
    // X tile -> fp16 (relu fused)
    int row0 = blockIdx.x * 64;
    constexpr int K4 = K / 4;
    for (int i = t; i < 64 * K4; i += 256) {
        int r = i / K4, c4 = (i % K4) * 4;
        int gr = row0 + r;
        float4 v = make_float4(0.f, 0.f, 0.f, 0.f);
        if (gr < M) v = ((const float4*)X)[(size_t)gr * K4 + (c4 >> 2)];
        if (RELU) {
            v.x = fmaxf(v.x, 0.f); v.y = fmaxf(v.y, 0.f);
            v.z = fmaxf(v.z, 0.f); v.w = fmaxf(v.w, 0.f);
        }
        __half2* dst = (__half2*)(Xs + r * KS + c4);
        dst[0] = __floats2half2_rn(v.x, v.y);
        dst[1] = __floats2half2_rn(v.z, v.w);
    }
    __syncthreads();

    int wid = t >> 5, lane = t & 31;
    int gid = lane >> 2, tig = lane & 3;
    int rowbase = (wid & 3) * 16;
    int colbase = (wid >> 2) * (N / 2);

    float acc[CHUNKS][4];
#pragma unroll
    for (int c = 0; c < CHUNKS; c++)
#pragma unroll
        for (int j = 0; j < 4; j++) acc[c][j] = 0.f;

#pragma unroll
    for (int ks = 0; ks < K / 16; ks++) {
        int kb = ks * 16;
        const __half* xp = Xs + (rowbase + gid) * KS + kb + 2 * tig;
        unsigned a0 = *(const unsigned*)xp;                 // (gid,   kb+2tig..+1)
        unsigned a1 = *(const unsigned*)(xp + 8 * KS);      // (gid+8, kb+2tig..+1)
        unsigned a2 = *(const unsigned*)(xp + 8);           // (gid,   kb+8+2tig..)
        unsigned a3 = *(const unsigned*)(xp + 8 * KS + 8);  // (gid+8, kb+8+2tig..)
#pragma unroll
        for (int ch = 0; ch < CHUNKS; ch++) {
            const __half* wp = Ws + (colbase + ch * 8 + gid) * KS + kb + 2 * tig;
            unsigned b0 = *(const unsigned*)wp;             // (k=kb+2tig..,   n)
            unsigned b1 = *(const unsigned*)(wp + 8);       // (k=kb+8+2tig.., n)
            asm volatile(
                "mma.sync.aligned.m16n8k16.row.col.f32.f16.f16.f32 "
                "{%0,%1,%2,%3}, {%4,%5,%6,%7}, {%8,%9}, {%0,%1,%2,%3};"
                : "+f"(acc[ch][0]), "+f"(acc[ch][1]), "+f"(acc[ch][2]), "+f"(acc[ch][3])
                : "r"(a0), "r"(a1), "r"(a2), "r"(a3), "r"(b0), "r"(b1));
        }
    }

    // c0=(gid,2tig) c1=(gid,2tig+1) c2=(gid+8,2tig) c3=(gid+8,2tig+1)
    int r0 = row0 + rowbase + gid;
    int r1 = r0 + 8;
    float s0 = (r0 < M) ? scale[r0] : 0.f;
    float s1 = (r1 < M) ? scale[r1] : 0.f;
#pragma unroll
    for (int ch = 0; ch < CHUNKS; ch++) {
        int gn = colbase + ch * 8 + 2 * tig;
        if (HALF_OUT) {
            __half* Yh = (__half*)Y;
            if (r0 < M) {
                __half2 p = __floats2half2_rn(acc[ch][0] * s0, acc[ch][1] * s0);
                *(__half2*)(Yh + (size_t)r0 * N + gn) = p;
            }
            if (r1 < M) {
                __half2 p = __floats2half2_rn(acc[ch][2] * s1, acc[ch][3] * s1);
                *(__half2*)(Yh + (size_t)r1 * N + gn) = p;
            }
        } else {
            if (r0 < M)
                *(float2*)(Y + (size_t)r0 * N + gn) = make_float2(acc[ch][0] * s0, acc[ch][1] * s0);
            if (r1 < M)
                *(float2*)(Y + (size_t)r1 * N + gn) = make_float2(acc[ch][2] * s1, acc[ch][3] * s1);
        }
    }
}

// ---------------------------------------------------------------------------
// Agg C=128 over fp16 h: TWO warps per node (R12, measured 36.6us).
__global__ void agg128_kernel(const int* __restrict__ deg, const int* __restrict__ csr,
                              const __half* __restrict__ h, const float* __restrict__ dinv,
                              const float* __restrict__ bias, float* __restrict__ out, int N) {
    int wp = (blockIdx.x * blockDim.x + threadIdx.x) >> 5;
    int lane = threadIdx.x & 31;
    int node = wp >> 1;
    int half = wp & 1;
    if (node >= N) return;
    int d = deg[node];
    int j = node * PAD, end = j + d;
    int col = half * 32 + lane;
    const unsigned* hv = (const unsigned*)h;
    float2 acc = make_float2(0.f, 0.f);
    for (; j + 8 <= end; j += 8) {
        int s[8];
#pragma unroll
        for (int u = 0; u < 8; u++) s[u] = csr[j + u];
        unsigned v[8];
#pragma unroll
        for (int u = 0; u < 8; u++) v[u] = hv[(size_t)s[u] * 64 + col];
#pragma unroll
        for (int u = 0; u < 8; u++) {
            float2 f = __half22float2(*(__half2*)&v[u]);
            acc.x += f.x; acc.y += f.y;
        }
    }
    for (; j < end; j++) {
        unsigned a = hv[(size_t)csr[j] * 64 + col];
        float2 f = __half22float2(*(__half2*)&a);
        acc.x += f.x; acc.y += f.y;
    }
    float dn = dinv[node];
    float2 bv = ((const float2*)bias)[col];
    float2 o = make_float2(acc.x * dn + bv.x, acc.y * dn + bv.y);
    ((float2*)out)[(size_t)node * 64 + col] = o;
}

// Agg C=64 over fp32 h: TWO warps per node (R12, known-good).
__global__ void agg64_kernel(const int* __restrict__ deg, const int* __restrict__ csr,
                             const float* __restrict__ h, const float* __restrict__ dinv,
                             const float* __restrict__ bias, float* __restrict__ out, int N) {
    int wp = (blockIdx.x * blockDim.x + threadIdx.x) >> 5;
    int lane = threadIdx.x & 31;
    int node = wp >> 1;
    int half = wp & 1;
    if (node >= N) return;
    int d = deg[node];
    int j = node * PAD, end = j + d;
    int col = half * 32 + lane;
    float acc = 0.f;
    for (; j + 8 <= end; j += 8) {
        int s[8];
#pragma unroll
        for (int u = 0; u < 8; u++) s[u] = csr[j + u];
        float v[8];
#pragma unroll
        for (int u = 0; u < 8; u++) v[u] = h[(size_t)s[u] * 64 + col];
#pragma unroll
        for (int u = 0; u < 8; u++) acc += v[u];
    }
    for (; j < end; j++) acc += h[(size_t)csr[j] * 64 + col];
    out[(size_t)node * 64 + col] = acc * dinv[node] + bias[col];
}

// ---------------------------------------------------------------------------
extern "C" void kernel_launch(void* const* d_in, const int* in_sizes, int n_in,
                              void* d_out, int out_size) {
    const float* x  = (const float*)d_in[0];
    const int*   ei = (const int*)d_in[1];
    const float* W1 = (const float*)d_in[2];
    const float* b1 = (const float*)d_in[3];
    const float* W2 = (const float*)d_in[4];
    const float* b2 = (const float*)d_in[5];
    float* out = (float*)d_out;

    const int N = in_sizes[0] / IN_DIM;
    const int E = in_sizes[1] / 2;
    const int* src = ei;
    const int* dst = ei + E;

    int *p_cnt, *p_cursor, *p_deg, *p_csr;
    float *p_dinv, *p_acc1, *p_h2;
    __half* p_h1;
    cudaGetSymbolAddress((void**)&p_cnt,    g_cnt);
    cudaGetSymbolAddress((void**)&p_cursor, g_cursor);
    cudaGetSymbolAddress((void**)&p_deg,    g_deg);
    cudaGetSymbolAddress((void**)&p_csr,    g_csr);
    cudaGetSymbolAddress((void**)&p_dinv,   g_dinv);
    cudaGetSymbolAddress((void**)&p_h1,     g_h1);
    cudaGetSymbolAddress((void**)&p_acc1,   g_acc1);
    cudaGetSymbolAddress((void**)&p_h2,     g_h2);

    // smem (halves): gemm1 = (128 + 64)*(128+8)*2 = 52.2 KB ; gemm2 = (64+64)*136*2 = 34.8 KB
    const int smem1 = (HID_DIM + 64) * (IN_DIM + 8) * 2;
    const int smem2 = (OUT_DIM + 64) * (HID_DIM + 8) * 2;
    cudaFuncSetAttribute((const void*)gemm_h16_kernel<IN_DIM, HID_DIM, false, true>,
                         cudaFuncAttributeMaxDynamicSharedMemorySize, smem1);
    cudaFuncSetAttribute((const void*)gemm_h16_kernel<HID_DIM, OUT_DIM, true, false>,
                         cudaFuncAttributeMaxDynamicSharedMemorySize, smem2);

    // One-time stream/event setup (first call is outside graph capture).
    static cudaStream_t s_side = nullptr;
    static cudaEvent_t  s_fork = nullptr, s_join = nullptr;
    if (!s_side) {
        cudaStreamCreateWithFlags(&s_side, cudaStreamNonBlocking);
        cudaEventCreateWithFlags(&s_fork, cudaEventDisableTiming);
        cudaEventCreateWithFlags(&s_join, cudaEventDisableTiming);
    }

    // --- serial prefix: deg -> dinv (zeroes cnt for next call, cursor for fill) ---
    deg_kernel<<<(E + 255) / 256, 256>>>(dst, p_cnt, E);
    dinv_kernel<<<(N + 255) / 256, 256>>>(p_cnt, p_cursor, p_deg, p_dinv, N);

    // --- fork: fill on side stream || GEMM1 (needs dinv only) on main ---
    cudaEventRecord(s_fork, 0);
    cudaStreamWaitEvent(s_side, s_fork, 0);
    fill_kernel<<<(E + 255) / 256, 256, 0, s_side>>>(src, dst, p_cursor, p_csr, E);
    cudaEventRecord(s_join, s_side);

    gemm_h16_kernel<IN_DIM, HID_DIM, false, true>
        <<<(N + 63) / 64, 256, smem1>>>(x, W1, p_dinv, (float*)p_h1, N);

    cudaStreamWaitEvent(0, s_join, 0);

    // --- layer 1 aggregation ---
    agg128_kernel<<<(N * 2 * 32 + 255) / 256, 256>>>(p_deg, p_csr, p_h1, p_dinv, b1, p_acc1, N);

    // --- layer 2 ---
    gemm_h16_kernel<HID_DIM, OUT_DIM, true, false>
        <<<(N + 63) / 64, 256, smem2>>>(p_acc1, W2, p_dinv, p_h2, N);
    agg64_kernel<<<(N * 2 * 32 + 255) / 256, 256>>>(p_deg, p_csr, p_h2, p_dinv, b2, out, N);
}

// round 17
// speedup vs baseline: 1.3590x; 1.1218x over previous
#include <cuda_runtime.h>
#include <cuda_fp16.h>
#include <cstdint>

// N_NODES=50000, N_EDGES=800000, IN=128, HID=128, OUT=64. int32 edge indices.
#define NMAX 50048
#define PAD 64
#define IN_DIM 128
#define HID_DIM 128
#define OUT_DIM 64

__device__ int    g_cnt[NMAX];
__device__ int    g_cursor[NMAX];
__device__ int    g_deg[NMAX];
__device__ int    g_csr[NMAX * PAD];
__device__ float  g_dinv[NMAX];
__device__ __half g_h1[NMAX * HID_DIM];
__device__ float  g_acc1[NMAX * HID_DIM];
__device__ float  g_h2[NMAX * OUT_DIM];

// ---------------------------------------------------------------------------
__global__ void deg_kernel(const int* __restrict__ dst, int* __restrict__ cnt, int E) {
    int i = blockIdx.x * blockDim.x + threadIdx.x;
    if (i < E) atomicAdd(&cnt[dst[i]], 1);
}

__global__ void dinv_kernel(int* __restrict__ cnt, int* __restrict__ cursor,
                            int* __restrict__ deg, float* __restrict__ dinv, int N) {
    int i = blockIdx.x * blockDim.x + threadIdx.x;
    if (i < N) {
        int d = cnt[i];
        deg[i] = min(d, PAD);
        dinv[i] = d > 0 ? rsqrtf((float)d) : 0.0f;
        cnt[i] = 0;
        cursor[i] = 0;
    }
}

__global__ void fill_kernel(const int* __restrict__ src, const int* __restrict__ dst,
                            int* __restrict__ cursor, int* __restrict__ csr, int E) {
    int e = blockIdx.x * blockDim.x + threadIdx.x;
    if (e < E) {
        int d = dst[e];
        int pos = atomicAdd(&cursor[d], 1);
        if (pos < PAD) csr[d * PAD + pos] = src[e];
    }
}

// ---------------------------------------------------------------------------
__device__ __forceinline__ void ldsm_x4(unsigned r[4], unsigned addr) {
    asm volatile("ldmatrix.sync.aligned.m8n8.x4.shared.b16 {%0,%1,%2,%3}, [%4];"
                 : "=r"(r[0]), "=r"(r[1]), "=r"(r[2]), "=r"(r[3]) : "r"(addr));
}
__device__ __forceinline__ void ldsm_x4_t(unsigned r[4], unsigned addr) {
    asm volatile("ldmatrix.sync.aligned.m8n8.x4.trans.shared.b16 {%0,%1,%2,%3}, [%4];"
                 : "=r"(r[0]), "=r"(r[1]), "=r"(r[2]), "=r"(r[3]) : "r"(addr));
}

// fp16 tensor-core GEMM: Y[M,N] = act(X)[M,K] @ W[K,N], Y[row] *= scale[row].
// W stored ROW-MAJOR fp16 (coalesced STS.64, no transpose). A fragments via
// ldmatrix.x4; B fragments via ldmatrix.x4.trans (2 N-chunks per instruction).
// Row strides K+8 / N+8 halves -> LDSM rows land banks +4 apart (conflict-free).
template <int K, int N, bool RELU, bool HALF_OUT>
__global__ void gemm_h16_kernel(const float* __restrict__ X, const float* __restrict__ W,
                                const float* __restrict__ scale,
                                float* __restrict__ Y, int M) {
    constexpr int KS = K + 8;                 // Xs row stride (halves)
    constexpr int NS = N + 8;                 // Ws row stride (halves)
    constexpr int CHUNKS = N / 16;            // 8 (N=128) / 4 (N=64)
    extern __shared__ __half smh[];
    __half* Ws = smh;                         // K * NS   (row-major W)
    __half* Xs = smh + K * NS;                // 64 * KS

    int t = threadIdx.x;
    // W[k][n] fp16, row-major, coalesced 8B stores
    for (int i = t; i < K * N / 4; i += 256) {
        int k = i / (N / 4), n4 = (i % (N / 4)) * 4;
        float4 w = ((const float4*)W)[i];
        __half2* dst = (__half2*)(Ws + k * NS + n4);
        dst[0] = __floats2half2_rn(w.x, w.y);
        dst[1] = __floats2half2_rn(w.z, w.w);
    }
    // X tile fp16 (relu fused), coalesced 8B stores
    int row0 = blockIdx.x * 64;
    constexpr int K4 = K / 4;
    for (int i = t; i < 64 * K4; i += 256) {
        int r = i / K4, c4 = (i % K4) * 4;
        int gr = row0 + r;
        float4 v = make_float4(0.f, 0.f, 0.f, 0.f);
        if (gr < M) v = ((const float4*)X)[(size_t)gr * K4 + (c4 >> 2)];
        if (RELU) {
            v.x = fmaxf(v.x, 0.f); v.y = fmaxf(v.y, 0.f);
            v.z = fmaxf(v.z, 0.f); v.w = fmaxf(v.w, 0.f);
        }
        __half2* dst = (__half2*)(Xs + r * KS + c4);
        dst[0] = __floats2half2_rn(v.x, v.y);
        dst[1] = __floats2half2_rn(v.z, v.w);
    }
    __syncthreads();

    int wid = t >> 5, lane = t & 31;
    int gid = lane >> 2, tig = lane & 3;
    int rowbase = (wid & 3) * 16;
    int colbase = (wid >> 2) * (N / 2);

    unsigned XsBase = (unsigned)__cvta_generic_to_shared(Xs);
    unsigned WsBase = (unsigned)__cvta_generic_to_shared(Ws);

    // ldmatrix lane-address components
    int lrow8 = (lane & 7) + ((lane >> 3) & 1) * 8;   // 0..15 pattern
    // A: lanes 0-15 -> rows rowbase+lrow8 @ k=kb; lanes 16-31 -> same rows @ kb+8
    unsigned addrA0 = XsBase +
        ((rowbase + lrow8) * KS + ((lane >> 4) * 8)) * 2;
    // B: lanes 0-15 -> k rows kb+lrow8 @ n0; lanes 16-31 -> same @ n0+8
    unsigned addrB0 = WsBase +
        (lrow8 * NS + ((lane >> 4) & 1) * 8) * 2;

    float acc[CHUNKS][4];
#pragma unroll
    for (int c = 0; c < CHUNKS; c++)
#pragma unroll
        for (int j = 0; j < 4; j++) acc[c][j] = 0.f;

#pragma unroll
    for (int ks = 0; ks < K / 16; ks++) {
        int kb = ks * 16;
        unsigned a[4];
        ldsm_x4(a, addrA0 + kb * 2);                   // a0..a3 fragments
#pragma unroll
        for (int cp = 0; cp < CHUNKS / 2; cp++) {
            int n0 = colbase + cp * 16;
            unsigned b[4];                             // b0,b1 chunk 2cp; b0,b1 chunk 2cp+1
            ldsm_x4_t(b, addrB0 + (kb * NS + n0) * 2);
            asm volatile(
                "mma.sync.aligned.m16n8k16.row.col.f32.f16.f16.f32 "
                "{%0,%1,%2,%3}, {%4,%5,%6,%7}, {%8,%9}, {%0,%1,%2,%3};"
                : "+f"(acc[2*cp][0]), "+f"(acc[2*cp][1]), "+f"(acc[2*cp][2]), "+f"(acc[2*cp][3])
                : "r"(a[0]), "r"(a[1]), "r"(a[2]), "r"(a[3]), "r"(b[0]), "r"(b[1]));
            asm volatile(
                "mma.sync.aligned.m16n8k16.row.col.f32.f16.f16.f32 "
                "{%0,%1,%2,%3}, {%4,%5,%6,%7}, {%8,%9}, {%0,%1,%2,%3};"
                : "+f"(acc[2*cp+1][0]), "+f"(acc[2*cp+1][1]), "+f"(acc[2*cp+1][2]), "+f"(acc[2*cp+1][3])
                : "r"(a[0]), "r"(a[1]), "r"(a[2]), "r"(a[3]), "r"(b[2]), "r"(b[3]));
        }
    }

    // c0=(gid,2tig) c1=(gid,2tig+1) c2=(gid+8,2tig) c3=(gid+8,2tig+1)
    int r0 = row0 + rowbase + gid;
    int r1 = r0 + 8;
    float s0 = (r0 < M) ? scale[r0] : 0.f;
    float s1 = (r1 < M) ? scale[r1] : 0.f;
#pragma unroll
    for (int ch = 0; ch < CHUNKS; ch++) {
        int gn = colbase + ch * 8 + 2 * tig;
        if (HALF_OUT) {
            __half* Yh = (__half*)Y;
            if (r0 < M) {
                __half2 p = __floats2half2_rn(acc[ch][0] * s0, acc[ch][1] * s0);
                *(__half2*)(Yh + (size_t)r0 * N + gn) = p;
            }
            if (r1 < M) {
                __half2 p = __floats2half2_rn(acc[ch][2] * s1, acc[ch][3] * s1);
                *(__half2*)(Yh + (size_t)r1 * N + gn) = p;
            }
        } else {
            if (r0 < M)
                *(float2*)(Y + (size_t)r0 * N + gn) = make_float2(acc[ch][0] * s0, acc[ch][1] * s0);
            if (r1 < M)
                *(float2*)(Y + (size_t)r1 * N + gn) = make_float2(acc[ch][2] * s1, acc[ch][3] * s1);
        }
    }
}

// ---------------------------------------------------------------------------
// Agg C=128 over fp16 h: TWO warps per node (R12, measured 36.6us).
__global__ void agg128_kernel(const int* __restrict__ deg, const int* __restrict__ csr,
                              const __half* __restrict__ h, const float* __restrict__ dinv,
                              const float* __restrict__ bias, float* __restrict__ out, int N) {
    int wp = (blockIdx.x * blockDim.x + threadIdx.x) >> 5;
    int lane = threadIdx.x & 31;
    int node = wp >> 1;
    int half = wp & 1;
    if (node >= N) return;
    int d = deg[node];
    int j = node * PAD, end = j + d;
    int col = half * 32 + lane;
    const unsigned* hv = (const unsigned*)h;
    float2 acc = make_float2(0.f, 0.f);
    for (; j + 8 <= end; j += 8) {
        int s[8];
#pragma unroll
        for (int u = 0; u < 8; u++) s[u] = csr[j + u];
        unsigned v[8];
#pragma unroll
        for (int u = 0; u < 8; u++) v[u] = hv[(size_t)s[u] * 64 + col];
#pragma unroll
        for (int u = 0; u < 8; u++) {
            float2 f = __half22float2(*(__half2*)&v[u]);
            acc.x += f.x; acc.y += f.y;
        }
    }
    for (; j < end; j++) {
        unsigned a = hv[(size_t)csr[j] * 64 + col];
        float2 f = __half22float2(*(__half2*)&a);
        acc.x += f.x; acc.y += f.y;
    }
    float dn = dinv[node];
    float2 bv = ((const float2*)bias)[col];
    float2 o = make_float2(acc.x * dn + bv.x, acc.y * dn + bv.y);
    ((float2*)out)[(size_t)node * 64 + col] = o;
}

// Agg C=64 over fp32 h: TWO warps per node (R12, known-good).
__global__ void agg64_kernel(const int* __restrict__ deg, const int* __restrict__ csr,
                             const float* __restrict__ h, const float* __restrict__ dinv,
                             const float* __restrict__ bias, float* __restrict__ out, int N) {
    int wp = (blockIdx.x * blockDim.x + threadIdx.x) >> 5;
    int lane = threadIdx.x & 31;
    int node = wp >> 1;
    int half = wp & 1;
    if (node >= N) return;
    int d = deg[node];
    int j = node * PAD, end = j + d;
    int col = half * 32 + lane;
    float acc = 0.f;
    for (; j + 8 <= end; j += 8) {
        int s[8];
#pragma unroll
        for (int u = 0; u < 8; u++) s[u] = csr[j + u];
        float v[8];
#pragma unroll
        for (int u = 0; u < 8; u++) v[u] = h[(size_t)s[u] * 64 + col];
#pragma unroll
        for (int u = 0; u < 8; u++) acc += v[u];
    }
    for (; j < end; j++) acc += h[(size_t)csr[j] * 64 + col];
    out[(size_t)node * 64 + col] = acc * dinv[node] + bias[col];
}

// ---------------------------------------------------------------------------
extern "C" void kernel_launch(void* const* d_in, const int* in_sizes, int n_in,
                              void* d_out, int out_size) {
    const float* x  = (const float*)d_in[0];
    const int*   ei = (const int*)d_in[1];
    const float* W1 = (const float*)d_in[2];
    const float* b1 = (const float*)d_in[3];
    const float* W2 = (const float*)d_in[4];
    const float* b2 = (const float*)d_in[5];
    float* out = (float*)d_out;

    const int N = in_sizes[0] / IN_DIM;
    const int E = in_sizes[1] / 2;
    const int* src = ei;
    const int* dst = ei + E;

    int *p_cnt, *p_cursor, *p_deg, *p_csr;
    float *p_dinv, *p_acc1, *p_h2;
    __half* p_h1;
    cudaGetSymbolAddress((void**)&p_cnt,    g_cnt);
    cudaGetSymbolAddress((void**)&p_cursor, g_cursor);
    cudaGetSymbolAddress((void**)&p_deg,    g_deg);
    cudaGetSymbolAddress((void**)&p_csr,    g_csr);
    cudaGetSymbolAddress((void**)&p_dinv,   g_dinv);
    cudaGetSymbolAddress((void**)&p_h1,     g_h1);
    cudaGetSymbolAddress((void**)&p_acc1,   g_acc1);
    cudaGetSymbolAddress((void**)&p_h2,     g_h2);

    // smem (halves): gemm1 = (128*(128+8) + 64*(128+8))*2 = 52.2 KB
    //                gemm2 = (128*(64+8) + 64*(128+8))*2 = 35.8 KB
    const int smem1 = (IN_DIM * (HID_DIM + 8) + 64 * (IN_DIM + 8)) * 2;
    const int smem2 = (HID_DIM * (OUT_DIM + 8) + 64 * (HID_DIM + 8)) * 2;
    cudaFuncSetAttribute((const void*)gemm_h16_kernel<IN_DIM, HID_DIM, false, true>,
                         cudaFuncAttributeMaxDynamicSharedMemorySize, smem1);
    cudaFuncSetAttribute((const void*)gemm_h16_kernel<HID_DIM, OUT_DIM, true, false>,
                         cudaFuncAttributeMaxDynamicSharedMemorySize, smem2);

    static cudaStream_t s_side = nullptr;
    static cudaEvent_t  s_fork = nullptr, s_join = nullptr;
    if (!s_side) {
        cudaStreamCreateWithFlags(&s_side, cudaStreamNonBlocking);
        cudaEventCreateWithFlags(&s_fork, cudaEventDisableTiming);
        cudaEventCreateWithFlags(&s_join, cudaEventDisableTiming);
    }

    // serial prefix: deg -> dinv (zeroes cnt for next call, cursor for fill)
    deg_kernel<<<(E + 255) / 256, 256>>>(dst, p_cnt, E);
    dinv_kernel<<<(N + 255) / 256, 256>>>(p_cnt, p_cursor, p_deg, p_dinv, N);

    // fork: fill || GEMM1
    cudaEventRecord(s_fork, 0);
    cudaStreamWaitEvent(s_side, s_fork, 0);
    fill_kernel<<<(E + 255) / 256, 256, 0, s_side>>>(src, dst, p_cursor, p_csr, E);
    cudaEventRecord(s_join, s_side);

    gemm_h16_kernel<IN_DIM, HID_DIM, false, true>
        <<<(N + 63) / 64, 256, smem1>>>(x, W1, p_dinv, (float*)p_h1, N);

    cudaStreamWaitEvent(0, s_join, 0);

    agg128_kernel<<<(N * 2 * 32 + 255) / 256, 256>>>(p_deg, p_csr, p_h1, p_dinv, b1, p_acc1, N);

    gemm_h16_kernel<HID_DIM, OUT_DIM, true, false>
        <<<(N + 63) / 64, 256, smem2>>>(p_acc1, W2, p_dinv, p_h2, N);
    agg64_kernel<<<(N * 2 * 32 + 255) / 256, 256>>>(p_deg, p_csr, p_h2, p_dinv, b2, out, N);
}